// round 15
// baseline (speedup 1.0000x reference)
#include <cuda_runtime.h>

#define LDIM 26
#define KCOMP 64
#define BN 262144
#define NITER 8
#define WFLOOR 1e-5f
#define VFLOOR 1e-6f
#define LOG_PI_C 47.784803726642978f   // 26 * log(2*pi)
#define SHIFT 40.0f                    // fixed logit shift (replaces per-row max)

#define NBLK_F 444            // fused blocks (256 thr), 3 per SM, one wave
#define TILE 32
#define NTILE (BN / TILE)     // 8192
#define NSLOT NBLK_F          // 444 partial slots (one per block)
#define NCHUNK 12
#define CSLOT (NSLOT / NCHUNK) // 37 slots per reduce chunk
#define PARTK 64              // floats per (slot,k): [0]=z, [4..31]=px, [32..59]=pxx
#define OUT_N (KCOMP + KCOMP*LDIM + KCOMP*LDIM*LDIM + 1)   // 44993

// ---------------- device state (no allocation allowed) ----------------
__device__ float g_w[KCOMP];
__device__ float g_mu[KCOMP * LDIM];
__device__ float g_sig[KCOMP * LDIM];
__device__ float g_Phn[KCOMP * LDIM];    // -0.5 / sigma
__device__ float g_MP[KCOMP * LDIM];     // mu / sigma
__device__ float g_C[KCOMP];             // log w - 0.5*(LOG_PI + logdet + quad) + SHIFT
__device__ float g_part[(size_t)NSLOT * KCOMP * PARTK];  // 7.3MB partials
__device__ float g_stat8[NCHUNK * KCOMP * PARTK];
__device__ float g_llp[NBLK_F];
__device__ float g_ll;

// ---------------- init: normalize w0, copy mu0 / sigma0 ----------------
__global__ void k_init(const float* __restrict__ w0,
                       const float* __restrict__ mu0,
                       const float* __restrict__ s0) {
    __shared__ float s_sum;
    if (threadIdx.x == 0) {
        float s = 0.f;
        for (int k = 0; k < KCOMP; k++) s += w0[k];
        s_sum = s;
    }
    __syncthreads();
    for (int i = threadIdx.x; i < KCOMP * LDIM; i += blockDim.x) {
        g_mu[i]  = mu0[i];
        g_sig[i] = s0[i];
    }
    if (threadIdx.x < KCOMP) g_w[threadIdx.x] = w0[threadIdx.x] / s_sum;
}

// ---------------- prep (initial only) ----------------
__global__ void k_prep() {
    int k = blockIdx.x;
    int lane = threadIdx.x;
    float ld = 0.f, qd = 0.f;
    if (lane < LDIM) {
        float sg = g_sig[k * LDIM + lane];
        float mu = g_mu[k * LDIM + lane];
        float pr = 1.0f / sg;
        g_Phn[k * LDIM + lane] = -0.5f * pr;
        g_MP[k * LDIM + lane] = mu * pr;
        ld = logf(sg);
        qd = mu * mu * pr;
    }
    #pragma unroll
    for (int o = 16; o; o >>= 1) {
        ld += __shfl_xor_sync(0xffffffffu, ld, o);
        qd += __shfl_xor_sync(0xffffffffu, qd, o);
    }
    if (lane == 0)
        g_C[k] = logf(g_w[k]) - 0.5f * (LOG_PI_C + ld + qd) + SHIFT;
}

// ---------------- FUSED E-step + M-step stats ------------------------------
// warp = (part = warp>>1, khalf = warp&1); lane owns comp k = khalf*32+lane.
// phase1: 8 rows (group = part) x logit+exp -> swizzled es[32][64]
// phase2: 8 threads/row sum e -> rs, ll
// phase3: ALL 32 rows; thread accumulates its (k, segment):
//   part0: px quads 0-3 (16)   part1: px quads 4-6 (12) + z
//   part2: pxx quads 0-3 (16)  part3: pxx quads 4-6 (12)
// Each (k,segment) owned by exactly one thread -> direct STG, no combine tree.
__global__ void __launch_bounds__(256, 3) k_fused(const float* __restrict__ x) {
    __shared__ __align__(16) float xs[TILE][28];
    __shared__ __align__(16) float x2s[TILE][28];
    __shared__ __align__(16) float es[TILE * KCOMP];
    __shared__ float rs_s[TILE];
    __shared__ float lls[TILE];

    int tid = threadIdx.x;
    int lane = tid & 31;
    int warp = tid >> 5;
    int khalf = warp & 1;
    int part = warp >> 1;                // 0..3
    int kp = (khalf << 5) + lane;        // owned comp
    int kq = kp >> 2, k3 = kp & 3;
    int r2 = tid >> 3, j8 = tid & 7;     // phase2 mapping

    float MP[LDIM], Ph[LDIM];
    #pragma unroll
    for (int l = 0; l < LDIM; l++) {
        MP[l] = g_MP[kp * LDIM + l];
        Ph[l] = g_Phn[kp * LDIM + l];
    }
    float C = g_C[kp];

    float llacc = 0.f;
    float z = 0.f;
    float acc[16];
    #pragma unroll
    for (int j = 0; j < 16; j++) acc[j] = 0.f;

    for (int t = blockIdx.x; t < NTILE; t += NBLK_F) {
        int rowbase = t * TILE;
        __syncthreads();                 // protect es/xs from previous tile
        // ---- stage 32 rows x 26 floats = 208 float4 ----
        if (tid < 208) {
            float4 v = ((const float4*)(x + (size_t)rowbase * LDIM))[tid];
            int e = tid * 4;
            float vv[4] = {v.x, v.y, v.z, v.w};
            #pragma unroll
            for (int j = 0; j < 4; j++) {
                int idx = e + j;
                int r = idx / LDIM, c = idx % LDIM;
                xs[r][c] = vv[j];
                x2s[r][c] = vv[j] * vv[j];
            }
        }
        if (tid < TILE) {
            xs[tid][26] = 0.f;  xs[tid][27] = 0.f;
            x2s[tid][26] = 0.f; x2s[tid][27] = 0.f;
        }
        __syncthreads();
        // ---- phase 1: logits + exp, 8 rows per warp (group = part) ----
        #pragma unroll 2
        for (int it = 0; it < 8; it++) {
            int r = (part << 3) + it;
            const float4* A = (const float4*)xs[r];
            float n = C;
            #pragma unroll
            for (int i = 0; i < 6; i++) {
                float4 a = A[i];
                #pragma unroll
                for (int j = 0; j < 4; j++) {
                    int l = 4 * i + j;
                    float av = j == 0 ? a.x : j == 1 ? a.y : j == 2 ? a.z : a.w;
                    float t0 = fmaf(av, Ph[l], MP[l]);
                    n = fmaf(av, t0, n);
                }
            }
            float2 a2 = *(const float2*)(&xs[r][24]);
            float u0 = fmaf(a2.x, Ph[24], MP[24]); n = fmaf(a2.x, u0, n);
            float u1 = fmaf(a2.y, Ph[25], MP[25]); n = fmaf(a2.y, u1, n);
            es[(r << 6) + ((kq ^ (r & 7)) << 2) + k3] = __expf(n);
        }
        __syncthreads();
        // ---- phase 2: row sums -> rs, ll ----
        {
            const float4* e4 = (const float4*)es;
            int qb = (r2 << 4) + (j8 << 1);
            float4 u = e4[qb];
            float4 v = e4[qb + 1];
            float s = ((u.x + u.y) + (u.z + u.w)) + ((v.x + v.y) + (v.z + v.w));
            s += __shfl_xor_sync(0xffffffffu, s, 1);
            s += __shfl_xor_sync(0xffffffffu, s, 2);
            s += __shfl_xor_sync(0xffffffffu, s, 4);
            if (j8 == 0) {
                rs_s[r2] = __frcp_rn(s);
                llacc += __logf(s) - SHIFT;
            }
        }
        __syncthreads();
        // ---- phase 3: segment accumulation over all 32 rows ----
        if ((part & 1) == 0) {
            const float (*B)[28] = (part == 0) ? xs : x2s;
            #pragma unroll 4
            for (int r = 0; r < TILE; r++) {
                float e = es[(r << 6) + ((kq ^ (r & 7)) << 2) + k3];
                float p = e * rs_s[r];
                const float4* V = (const float4*)B[r];
                float4 v0 = V[0], v1 = V[1], v2 = V[2], v3 = V[3];
                acc[0]  = fmaf(p, v0.x, acc[0]);
                acc[1]  = fmaf(p, v0.y, acc[1]);
                acc[2]  = fmaf(p, v0.z, acc[2]);
                acc[3]  = fmaf(p, v0.w, acc[3]);
                acc[4]  = fmaf(p, v1.x, acc[4]);
                acc[5]  = fmaf(p, v1.y, acc[5]);
                acc[6]  = fmaf(p, v1.z, acc[6]);
                acc[7]  = fmaf(p, v1.w, acc[7]);
                acc[8]  = fmaf(p, v2.x, acc[8]);
                acc[9]  = fmaf(p, v2.y, acc[9]);
                acc[10] = fmaf(p, v2.z, acc[10]);
                acc[11] = fmaf(p, v2.w, acc[11]);
                acc[12] = fmaf(p, v3.x, acc[12]);
                acc[13] = fmaf(p, v3.y, acc[13]);
                acc[14] = fmaf(p, v3.z, acc[14]);
                acc[15] = fmaf(p, v3.w, acc[15]);
            }
        } else {
            const float (*B)[28] = (part == 1) ? xs : x2s;
            #pragma unroll 4
            for (int r = 0; r < TILE; r++) {
                float e = es[(r << 6) + ((kq ^ (r & 7)) << 2) + k3];
                float p = e * rs_s[r];
                z += p;
                const float4* V = (const float4*)B[r];
                float4 v4 = V[4], v5 = V[5], v6 = V[6];
                acc[0]  = fmaf(p, v4.x, acc[0]);
                acc[1]  = fmaf(p, v4.y, acc[1]);
                acc[2]  = fmaf(p, v4.z, acc[2]);
                acc[3]  = fmaf(p, v4.w, acc[3]);
                acc[4]  = fmaf(p, v5.x, acc[4]);
                acc[5]  = fmaf(p, v5.y, acc[5]);
                acc[6]  = fmaf(p, v5.z, acc[6]);
                acc[7]  = fmaf(p, v5.w, acc[7]);
                acc[8]  = fmaf(p, v6.x, acc[8]);
                acc[9]  = fmaf(p, v6.y, acc[9]);
                acc[10] = fmaf(p, v6.z, acc[10]);
                acc[11] = fmaf(p, v6.w, acc[11]);
            }
        }
    }

    // ---- ll gather ----
    __syncthreads();
    if (j8 == 0) lls[r2] = llacc;
    __syncthreads();
    if (tid == 0) {
        float s = 0.f;
        for (int i = 0; i < TILE; i++) s += lls[i];
        g_llp[blockIdx.x] = s;
    }

    // ---- direct segment store (each (k,part) owned by one thread) ----
    {
        float* dst = g_part + ((size_t)blockIdx.x * KCOMP + kp) * PARTK;
        float4* d4 = (float4*)dst;
        if (part == 0) {
            d4[1] = make_float4(acc[0], acc[1], acc[2], acc[3]);
            d4[2] = make_float4(acc[4], acc[5], acc[6], acc[7]);
            d4[3] = make_float4(acc[8], acc[9], acc[10], acc[11]);
            d4[4] = make_float4(acc[12], acc[13], acc[14], acc[15]);
        } else if (part == 1) {
            dst[0] = z;
            d4[5] = make_float4(acc[0], acc[1], acc[2], acc[3]);
            d4[6] = make_float4(acc[4], acc[5], acc[6], acc[7]);
            d4[7] = make_float4(acc[8], acc[9], acc[10], acc[11]);
        } else if (part == 2) {
            d4[8]  = make_float4(acc[0], acc[1], acc[2], acc[3]);
            d4[9]  = make_float4(acc[4], acc[5], acc[6], acc[7]);
            d4[10] = make_float4(acc[8], acc[9], acc[10], acc[11]);
            d4[11] = make_float4(acc[12], acc[13], acc[14], acc[15]);
        } else {
            d4[12] = make_float4(acc[0], acc[1], acc[2], acc[3]);
            d4[13] = make_float4(acc[4], acc[5], acc[6], acc[7]);
            d4[14] = make_float4(acc[8], acc[9], acc[10], acc[11]);
        }
    }
}

// ---------------- reduce partials: one block per (k, chunk) ----------------
__global__ void __launch_bounds__(64) k_reduce() {
    int chunk = blockIdx.x >> 6;
    int bk = blockIdx.x & 63;
    int j = threadIdx.x;
    bool live = (j == 0) || (j >= 4 && j < 60);
    if (live) {
        float acc = 0.f;
        int base = chunk * CSLOT;
        #pragma unroll 4
        for (int s = 0; s < CSLOT; s++)
            acc += g_part[((size_t)(base + s) * KCOMP + bk) * PARTK + j];
        g_stat8[(chunk * KCOMP + bk) * PARTK + j] = acc;
    }
}

// ---------------- M-step finalize + fused prep ----------------
__global__ void __launch_bounds__(256) k_mstep() {
    __shared__ float s_w[KCOMP];
    __shared__ float s_z[KCOMP];
    __shared__ float s_ab[2];
    __shared__ float s_llp[64];
    int tid = threadIdx.x;

    if (tid < KCOMP) {
        float zk = 0.f;
        #pragma unroll
        for (int c = 0; c < NCHUNK; c++) zk += g_stat8[(c * KCOMP + tid) * PARTK];
        s_z[tid] = zk;
        s_w[tid] = fmaxf(zk * (1.0f / BN), WFLOOR);
        float l = 0.f;
        for (int i = tid; i < NBLK_F; i += 64) l += g_llp[i];
        s_llp[tid] = l;
    }
    __syncthreads();
    if (tid == 0) {
        float sum = 0.f, ll = 0.f;
        for (int k = 0; k < KCOMP; k++) { sum += s_w[k]; ll += s_llp[k]; }
        float sf = WFLOOR * KCOMP;
        float a = (1.0f - sf) / (sum - sf);
        s_ab[0] = a;
        s_ab[1] = WFLOOR * (1.0f - a);
        g_ll = ll;
    }
    __syncthreads();
    if (tid < KCOMP) g_w[tid] = s_ab[0] * s_w[tid] + s_ab[1];

    for (int idx = tid; idx < KCOMP * LDIM; idx += 256) {
        int k = idx / LDIM, l = idx % LDIM;
        float zi = 1.0f / s_z[k];
        float px = 0.f, pxx = 0.f;
        #pragma unroll
        for (int c = 0; c < NCHUNK; c++) {
            px  += g_stat8[(c * KCOMP + k) * PARTK + 4 + l];
            pxx += g_stat8[(c * KCOMP + k) * PARTK + 32 + l];
        }
        float mu = px * zi;
        float sg = fmaxf(pxx * zi - mu * mu, VFLOOR);
        g_mu[idx] = mu;
        g_sig[idx] = sg;
    }
    __syncthreads();

    int warp = tid >> 5, lane = tid & 31;
    for (int k = warp; k < KCOMP; k += 8) {
        float ld = 0.f, qd = 0.f;
        if (lane < LDIM) {
            float sg = g_sig[k * LDIM + lane];
            float mu = g_mu[k * LDIM + lane];
            float pr = 1.0f / sg;
            g_Phn[k * LDIM + lane] = -0.5f * pr;
            g_MP[k * LDIM + lane] = mu * pr;
            ld = logf(sg);
            qd = mu * mu * pr;
        }
        #pragma unroll
        for (int o = 16; o; o >>= 1) {
            ld += __shfl_xor_sync(0xffffffffu, ld, o);
            qd += __shfl_xor_sync(0xffffffffu, qd, o);
        }
        if (lane == 0)
            g_C[k] = logf(g_w[k]) - 0.5f * (LOG_PI_C + ld + qd) + SHIFT;
    }
}

// ---------------- output: w | mu | diag-expanded sigma | ll ----------------
__global__ void k_write(float* __restrict__ out) {
    int i = blockIdx.x * 256 + threadIdx.x;
    if (i >= OUT_N) return;
    float v;
    if (i < KCOMP) {
        v = g_w[i];
    } else if (i < KCOMP + KCOMP * LDIM) {
        v = g_mu[i - KCOMP];
    } else if (i < KCOMP + KCOMP * LDIM + KCOMP * LDIM * LDIM) {
        int j = i - (KCOMP + KCOMP * LDIM);
        int k = j / (LDIM * LDIM);
        int rc = j % (LDIM * LDIM);
        int r = rc / LDIM, c = rc % LDIM;
        v = (r == c) ? g_sig[k * LDIM + r] : 0.f;
    } else {
        v = g_ll;
    }
    out[i] = v;
}

extern "C" void kernel_launch(void* const* d_in, const int* in_sizes, int n_in,
                              void* d_out, int out_size) {
    const float* x   = (const float*)d_in[0];
    const float* w0  = (const float*)d_in[1];
    const float* mu0 = (const float*)d_in[2];
    const float* s0  = (const float*)d_in[3];
    float* out = (float*)d_out;

    k_init<<<1, 256>>>(w0, mu0, s0);
    k_prep<<<KCOMP, 32>>>();
    for (int it = 0; it < NITER; it++) {
        k_fused<<<NBLK_F, 256>>>(x);
        k_reduce<<<KCOMP * NCHUNK, 64>>>();
        k_mstep<<<1, 256>>>();
    }
    k_write<<<(OUT_N + 255) / 256, 256>>>(out);
}

// round 16
// speedup vs baseline: 1.2305x; 1.2305x over previous
#include <cuda_runtime.h>

#define LDIM 26
#define KCOMP 64
#define BN 262144
#define NITER 8
#define WFLOOR 1e-5f
#define VFLOOR 1e-6f
#define LOG_PI_C 47.784803726642978f   // 26 * log(2*pi)
#define SHIFT 40.0f                    // fixed logit shift (replaces per-row max)

#define NBLK_F 296            // fused blocks (256 thr), 2 per SM, one wave
#define TILE 32
#define NTILE (BN / TILE)     // 8192
#define NSLOT NBLK_F          // 296 partial slots (one per block)
#define NCHUNK 8
#define CSLOT (NSLOT / NCHUNK) // 37 slots per reduce chunk
#define OUT_N (KCOMP + KCOMP*LDIM + KCOMP*LDIM*LDIM + 1)   // 44993

// ---------------- device state (no allocation allowed) ----------------
__device__ float g_w[KCOMP];
__device__ float g_mu[KCOMP * LDIM];
__device__ float g_sig[KCOMP * LDIM];
__device__ float g_Phn[KCOMP * LDIM];    // -0.5 / sigma
__device__ float g_MP[KCOMP * LDIM];     // mu / sigma
__device__ float g_C[KCOMP];             // log w - 0.5*(LOG_PI + logdet + quad) + SHIFT
__device__ float g_part[(size_t)NSLOT * KCOMP * 54];  // 4.1MB partials
__device__ float g_stat8[NCHUNK * KCOMP * 54];
__device__ float g_llp[NBLK_F];
__device__ float g_ll;

// ---------------- init: normalize w0, copy mu0 / sigma0 ----------------
__global__ void k_init(const float* __restrict__ w0,
                       const float* __restrict__ mu0,
                       const float* __restrict__ s0) {
    __shared__ float s_sum;
    if (threadIdx.x == 0) {
        float s = 0.f;
        for (int k = 0; k < KCOMP; k++) s += w0[k];
        s_sum = s;
    }
    __syncthreads();
    for (int i = threadIdx.x; i < KCOMP * LDIM; i += blockDim.x) {
        g_mu[i]  = mu0[i];
        g_sig[i] = s0[i];
    }
    if (threadIdx.x < KCOMP) g_w[threadIdx.x] = w0[threadIdx.x] / s_sum;
}

// ---------------- prep (initial only) ----------------
__global__ void k_prep() {
    int k = blockIdx.x;
    int lane = threadIdx.x;
    float ld = 0.f, qd = 0.f;
    if (lane < LDIM) {
        float sg = g_sig[k * LDIM + lane];
        float mu = g_mu[k * LDIM + lane];
        float pr = 1.0f / sg;
        g_Phn[k * LDIM + lane] = -0.5f * pr;
        g_MP[k * LDIM + lane] = mu * pr;
        ld = logf(sg);
        qd = mu * mu * pr;
    }
    #pragma unroll
    for (int o = 16; o; o >>= 1) {
        ld += __shfl_xor_sync(0xffffffffu, ld, o);
        qd += __shfl_xor_sync(0xffffffffu, qd, o);
    }
    if (lane == 0)
        g_C[k] = logf(g_w[k]) - 0.5f * (LOG_PI_C + ld + qd) + SHIFT;
}

// ---------------- FUSED E-step + M-step stats (round-13 proven) ------------
__global__ void __launch_bounds__(256, 2) k_fused(const float* __restrict__ x) {
    __shared__ __align__(16) float xs[TILE][28];
    __shared__ __align__(16) float x2s[TILE][28];
    __shared__ __align__(16) float es[TILE * KCOMP];
    __shared__ float rs_s[TILE];
    __shared__ float lls[TILE];
    __shared__ float comb[2][2][KCOMP][27];   // [slot][h][k][z|26 vals]

    int tid = threadIdx.x;
    int lane = tid & 31;
    int warp = tid >> 5;
    int khalf1 = warp & 1;
    int rq = warp >> 1;
    int kp = (khalf1 << 5) + lane;
    int kq = kp >> 2, k3 = kp & 3;
    int r2 = tid >> 3, j8 = tid & 7;
    int h = warp & 1;
    int rgrp = warp >> 1;
    int k0 = lane, k1 = lane + 32;
    int sq0 = lane >> 2, e30 = lane & 3;

    float MP[LDIM], Ph[LDIM];
    #pragma unroll
    for (int l = 0; l < LDIM; l++) {
        MP[l] = g_MP[kp * LDIM + l];
        Ph[l] = g_Phn[kp * LDIM + l];
    }
    float C = g_C[kp];

    float llacc = 0.f;
    float z0 = 0.f, z1 = 0.f;
    float a0[26], a1[26];
    #pragma unroll
    for (int j = 0; j < 26; j++) { a0[j] = 0.f; a1[j] = 0.f; }

    for (int t = blockIdx.x; t < NTILE; t += NBLK_F) {
        int rowbase = t * TILE;
        __syncthreads();
        if (tid < 208) {
            float4 v = ((const float4*)(x + (size_t)rowbase * LDIM))[tid];
            int e = tid * 4;
            float vv[4] = {v.x, v.y, v.z, v.w};
            #pragma unroll
            for (int j = 0; j < 4; j++) {
                int idx = e + j;
                int r = idx / LDIM, c = idx % LDIM;
                xs[r][c] = vv[j];
                x2s[r][c] = vv[j] * vv[j];
            }
        }
        __syncthreads();
        // ---- phase 1: logits + exp ----
        #pragma unroll
        for (int it = 0; it < 4; it++) {
            int ra = (rq << 3) + it * 2;
            int rb = ra + 1;
            const float4* A = (const float4*)xs[ra];
            const float4* B = (const float4*)xs[rb];
            float na = C, nb = C;
            #pragma unroll
            for (int i = 0; i < 6; i++) {
                float4 a = A[i];
                float4 b = B[i];
                #pragma unroll
                for (int j = 0; j < 4; j++) {
                    int l = 4 * i + j;
                    float av = j == 0 ? a.x : j == 1 ? a.y : j == 2 ? a.z : a.w;
                    float bv = j == 0 ? b.x : j == 1 ? b.y : j == 2 ? b.z : b.w;
                    float t0 = fmaf(av, Ph[l], MP[l]); na = fmaf(av, t0, na);
                    float t1 = fmaf(bv, Ph[l], MP[l]); nb = fmaf(bv, t1, nb);
                }
            }
            float2 a2 = *(const float2*)(&xs[ra][24]);
            float2 b2 = *(const float2*)(&xs[rb][24]);
            float u0 = fmaf(a2.x, Ph[24], MP[24]); na = fmaf(a2.x, u0, na);
            float u1 = fmaf(a2.y, Ph[25], MP[25]); na = fmaf(a2.y, u1, na);
            float u2 = fmaf(b2.x, Ph[24], MP[24]); nb = fmaf(b2.x, u2, nb);
            float u3 = fmaf(b2.y, Ph[25], MP[25]); nb = fmaf(b2.y, u3, nb);
            es[(ra << 6) + ((kq ^ (ra & 7)) << 2) + k3] = __expf(na);
            es[(rb << 6) + ((kq ^ (rb & 7)) << 2) + k3] = __expf(nb);
        }
        __syncthreads();
        // ---- phase 2: row sums -> rs, ll ----
        {
            const float4* e4 = (const float4*)es;
            int qb = (r2 << 4) + (j8 << 1);
            float4 u = e4[qb];
            float4 v = e4[qb + 1];
            float s = ((u.x + u.y) + (u.z + u.w)) + ((v.x + v.y) + (v.z + v.w));
            s += __shfl_xor_sync(0xffffffffu, s, 1);
            s += __shfl_xor_sync(0xffffffffu, s, 2);
            s += __shfl_xor_sync(0xffffffffu, s, 4);
            if (j8 == 0) {
                rs_s[r2] = __frcp_rn(s);
                llacc += __logf(s) - SHIFT;
            }
        }
        __syncthreads();
        // ---- phase 3: stats accumulation ----
        #pragma unroll
        for (int rr = 0; rr < 8; rr++) {
            int r = (rgrp << 3) + rr;
            float rsv = rs_s[r];
            int sw = ((sq0 ^ (r & 7)) << 2) + e30;
            float e0 = es[(r << 6) + sw];
            float e1 = es[(r << 6) + 32 + sw];
            float p0 = e0 * rsv;
            float p1 = e1 * rsv;
            if (h == 0) { z0 += p0; z1 += p1; }
            const float4* V = (const float4*)(h ? x2s[r] : xs[r]);
            #pragma unroll
            for (int i = 0; i < 6; i++) {
                float4 v = V[i];
                a0[4*i]   = fmaf(p0, v.x, a0[4*i]);
                a1[4*i]   = fmaf(p1, v.x, a1[4*i]);
                a0[4*i+1] = fmaf(p0, v.y, a0[4*i+1]);
                a1[4*i+1] = fmaf(p1, v.y, a1[4*i+1]);
                a0[4*i+2] = fmaf(p0, v.z, a0[4*i+2]);
                a1[4*i+2] = fmaf(p1, v.z, a1[4*i+2]);
                a0[4*i+3] = fmaf(p0, v.w, a0[4*i+3]);
                a1[4*i+3] = fmaf(p1, v.w, a1[4*i+3]);
            }
            float4 v6 = V[6];
            a0[24] = fmaf(p0, v6.x, a0[24]);
            a1[24] = fmaf(p1, v6.x, a1[24]);
            a0[25] = fmaf(p0, v6.y, a0[25]);
            a1[25] = fmaf(p1, v6.y, a1[25]);
        }
    }

    // ---- ll gather ----
    __syncthreads();
    if (j8 == 0) lls[r2] = llacc;
    __syncthreads();
    if (tid == 0) {
        float s = 0.f;
        for (int i = 0; i < TILE; i++) s += lls[i];
        g_llp[blockIdx.x] = s;
    }

    // ---- combine rgrps 0..3 -> rgrp 0, one partial slot per block ----
    if (rgrp >= 2) {
        int slot = rgrp - 2;
        comb[slot][h][k0][0] = z0;
        comb[slot][h][k1][0] = z1;
        #pragma unroll
        for (int j = 0; j < 26; j++) {
            comb[slot][h][k0][1 + j] = a0[j];
            comb[slot][h][k1][1 + j] = a1[j];
        }
    }
    __syncthreads();
    if (rgrp < 2) {
        z0 += comb[rgrp][h][k0][0];
        z1 += comb[rgrp][h][k1][0];
        #pragma unroll
        for (int j = 0; j < 26; j++) {
            a0[j] += comb[rgrp][h][k0][1 + j];
            a1[j] += comb[rgrp][h][k1][1 + j];
        }
    }
    __syncthreads();
    if (rgrp == 1) {
        comb[0][h][k0][0] = z0;
        comb[0][h][k1][0] = z1;
        #pragma unroll
        for (int j = 0; j < 26; j++) {
            comb[0][h][k0][1 + j] = a0[j];
            comb[0][h][k1][1 + j] = a1[j];
        }
    }
    __syncthreads();
    if (rgrp == 0) {
        z0 += comb[0][h][k0][0];
        z1 += comb[0][h][k1][0];
        #pragma unroll
        for (int j = 0; j < 26; j++) {
            a0[j] += comb[0][h][k0][1 + j];
            a1[j] += comb[0][h][k1][1 + j];
        }
        float* d0 = g_part + ((size_t)blockIdx.x * KCOMP + k0) * 54;
        float* d1 = g_part + ((size_t)blockIdx.x * KCOMP + k1) * 54;
        if (h == 0) {
            d0[0] = z0;
            d1[0] = z1;
            #pragma unroll
            for (int j = 0; j < 26; j++) { d0[1 + j] = a0[j]; d1[1 + j] = a1[j]; }
        } else {
            #pragma unroll
            for (int j = 0; j < 26; j++) { d0[27 + j] = a0[j]; d1[27 + j] = a1[j]; }
        }
    }
}

// ---------------- reduce partials: one block per (k, chunk) ----------------
__global__ void __launch_bounds__(64) k_reduce() {
    int chunk = blockIdx.x >> 6;   // 0..7
    int bk = blockIdx.x & 63;
    int j = threadIdx.x;
    if (j < 54) {
        float acc = 0.f;
        int base = chunk * CSLOT;
        #pragma unroll 4
        for (int s = 0; s < CSLOT; s++)
            acc += g_part[((size_t)(base + s) * KCOMP + bk) * 54 + j];
        g_stat8[(chunk * KCOMP + bk) * 54 + j] = acc;
    }
}

// ---------------- M-step finalize + fused prep ----------------
__global__ void __launch_bounds__(256) k_mstep() {
    __shared__ float s_w[KCOMP];
    __shared__ float s_z[KCOMP];
    __shared__ float s_ab[2];
    __shared__ float s_llp[64];
    int tid = threadIdx.x;

    if (tid < KCOMP) {
        float zk = 0.f;
        #pragma unroll
        for (int c = 0; c < NCHUNK; c++) zk += g_stat8[(c * KCOMP + tid) * 54];
        s_z[tid] = zk;
        s_w[tid] = fmaxf(zk * (1.0f / BN), WFLOOR);
        float l = 0.f;
        for (int i = tid; i < NBLK_F; i += 64) l += g_llp[i];
        s_llp[tid] = l;
    }
    __syncthreads();
    if (tid == 0) {
        float sum = 0.f, ll = 0.f;
        for (int k = 0; k < KCOMP; k++) { sum += s_w[k]; ll += s_llp[k]; }
        float sf = WFLOOR * KCOMP;
        float a = (1.0f - sf) / (sum - sf);
        s_ab[0] = a;
        s_ab[1] = WFLOOR * (1.0f - a);
        g_ll = ll;
    }
    __syncthreads();
    if (tid < KCOMP) g_w[tid] = s_ab[0] * s_w[tid] + s_ab[1];

    for (int idx = tid; idx < KCOMP * LDIM; idx += 256) {
        int k = idx / LDIM, l = idx % LDIM;
        float zi = 1.0f / s_z[k];
        float px = 0.f, pxx = 0.f;
        #pragma unroll
        for (int c = 0; c < NCHUNK; c++) {
            px  += g_stat8[(c * KCOMP + k) * 54 + 1 + l];
            pxx += g_stat8[(c * KCOMP + k) * 54 + 27 + l];
        }
        float mu = px * zi;
        float sg = fmaxf(pxx * zi - mu * mu, VFLOOR);
        g_mu[idx] = mu;
        g_sig[idx] = sg;
    }
    __syncthreads();

    int warp = tid >> 5, lane = tid & 31;
    for (int k = warp; k < KCOMP; k += 8) {
        float ld = 0.f, qd = 0.f;
        if (lane < LDIM) {
            float sg = g_sig[k * LDIM + lane];
            float mu = g_mu[k * LDIM + lane];
            float pr = 1.0f / sg;
            g_Phn[k * LDIM + lane] = -0.5f * pr;
            g_MP[k * LDIM + lane] = mu * pr;
            ld = logf(sg);
            qd = mu * mu * pr;
        }
        #pragma unroll
        for (int o = 16; o; o >>= 1) {
            ld += __shfl_xor_sync(0xffffffffu, ld, o);
            qd += __shfl_xor_sync(0xffffffffu, qd, o);
        }
        if (lane == 0)
            g_C[k] = logf(g_w[k]) - 0.5f * (LOG_PI_C + ld + qd) + SHIFT;
    }
}

// ---------------- output: w | mu | diag-expanded sigma | ll ----------------
__global__ void k_write(float* __restrict__ out) {
    int i = blockIdx.x * 256 + threadIdx.x;
    if (i >= OUT_N) return;
    float v;
    if (i < KCOMP) {
        v = g_w[i];
    } else if (i < KCOMP + KCOMP * LDIM) {
        v = g_mu[i - KCOMP];
    } else if (i < KCOMP + KCOMP * LDIM + KCOMP * LDIM * LDIM) {
        int j = i - (KCOMP + KCOMP * LDIM);
        int k = j / (LDIM * LDIM);
        int rc = j % (LDIM * LDIM);
        int r = rc / LDIM, c = rc % LDIM;
        v = (r == c) ? g_sig[k * LDIM + r] : 0.f;
    } else {
        v = g_ll;
    }
    out[i] = v;
}

extern "C" void kernel_launch(void* const* d_in, const int* in_sizes, int n_in,
                              void* d_out, int out_size) {
    const float* x   = (const float*)d_in[0];
    const float* w0  = (const float*)d_in[1];
    const float* mu0 = (const float*)d_in[2];
    const float* s0  = (const float*)d_in[3];
    float* out = (float*)d_out;

    k_init<<<1, 256>>>(w0, mu0, s0);
    k_prep<<<KCOMP, 32>>>();
    for (int it = 0; it < NITER; it++) {
        k_fused<<<NBLK_F, 256>>>(x);
        k_reduce<<<KCOMP * NCHUNK, 64>>>();
        k_mstep<<<1, 256>>>();
    }
    k_write<<<(OUT_N + 255) / 256, 256>>>(out);
}